// round 1
// baseline (speedup 1.0000x reference)
#include <cuda_runtime.h>
#include <cstdint>

// ---------------- problem constants ----------------
#define BATCH 8
#define C_IN 256
#define LEN 2048
#define D_INNER 512
#define DT_RANK 16
#define D_STATE 16
#define NROWS (BATCH * LEN)          // 16384

// ---------------- scratch buffers (device globals; no allocs allowed) ----------------
__device__ float g_x[NROWS * C_IN];          // layer input (B*L, 256)
__device__ float g_xz[NROWS * 1024];         // in_proj out: [xr | z]
__device__ float g_xc[NROWS * D_INNER];      // conv+silu out
__device__ float g_xdb[NROWS * 48];          // x_proj out (dt|B|C)
__device__ float g_delta[NROWS * D_INNER];   // softplus(dt_proj)
__device__ float g_y[NROWS * D_INNER];       // scan out / final pre-scatter

// ---------------- helpers ----------------
__device__ __forceinline__ float tf32_rna(float x) {
    uint32_t y;
    asm("cvt.rna.tf32.f32 %0, %1;" : "=r"(y) : "f"(x));
    return __uint_as_float(y);
}

__device__ __forceinline__ float silu_f(float v) {
    return v / (1.f + __expf(-v));
}

// EPI: 0 = none, 1 = bias + softplus, 2 = bias + relu
template<int EPI>
__device__ __forceinline__ float epi_apply(float v, float bv) {
    if (EPI == 1) {
        v += bv;
        return fmaxf(v, 0.f) + log1pf(__expf(-fabsf(v)));
    } else if (EPI == 2) {
        v += bv;
        return fmaxf(v, 0.f);
    }
    return v;
}

// ---------------- tf32 tensor-core GEMM: C[M,N] = A[M,K] @ W[N,K]^T ----------------
// BM=128, BN=64, 256 threads, 8 warps in 4x2, warp tile 32x32 (2x4 mma m16n8k8)
template<int BK, int EPI>
__global__ __launch_bounds__(256)
void gemm_tf32_kernel(const float* __restrict__ A, int lda,
                      const float* __restrict__ W,
                      const float* __restrict__ bias,
                      float* __restrict__ C, int ldc,
                      int N, int K)
{
    constexpr int BM = 128, BN = 64;
    constexpr int BKp = BK + 4;
    __shared__ float As[BM][BKp];
    __shared__ float Bs[BN][BKp];

    const int tid  = threadIdx.x;
    const int warp = tid >> 5, lane = tid & 31;
    const int wm = warp >> 1, wn = warp & 1;
    const int g = lane >> 2, tq = lane & 3;
    const int row0 = blockIdx.y * BM;
    const int col0 = blockIdx.x * BN;

    constexpr int AF4   = BK / 4;          // float4 per row
    constexpr int ARPP  = 256 / AF4;       // rows per pass
    constexpr int APASS = BM / ARPP;
    constexpr int BPASS = BN / ARPP;
    const int ar = tid / AF4;
    const int aq = tid % AF4;

    float4 pa[APASS], pb[BPASS > 0 ? BPASS : 1];
    const int ktiles = K / BK;

    auto ldtile = [&](int kt) {
        const int k0 = kt * BK;
        #pragma unroll
        for (int p = 0; p < APASS; p++) {
            const int r = ar + p * ARPP;
            pa[p] = *(const float4*)(A + (size_t)(row0 + r) * lda + k0 + aq * 4);
        }
        #pragma unroll
        for (int p = 0; p < BPASS; p++) {
            const int n = ar + p * ARPP;
            if (col0 + n < N)
                pb[p] = *(const float4*)(W + (size_t)(col0 + n) * K + k0 + aq * 4);
            else
                pb[p] = make_float4(0.f, 0.f, 0.f, 0.f);
        }
    };
    auto sttile = [&]() {
        #pragma unroll
        for (int p = 0; p < APASS; p++) {
            const int r = ar + p * ARPP;
            float4 v;
            v.x = tf32_rna(pa[p].x); v.y = tf32_rna(pa[p].y);
            v.z = tf32_rna(pa[p].z); v.w = tf32_rna(pa[p].w);
            *(float4*)&As[r][aq * 4] = v;
        }
        #pragma unroll
        for (int p = 0; p < BPASS; p++) {
            const int n = ar + p * ARPP;
            float4 v;
            v.x = tf32_rna(pb[p].x); v.y = tf32_rna(pb[p].y);
            v.z = tf32_rna(pb[p].z); v.w = tf32_rna(pb[p].w);
            *(float4*)&Bs[n][aq * 4] = v;
        }
    };

    float acc[2][4][4];
    #pragma unroll
    for (int mt = 0; mt < 2; mt++)
        #pragma unroll
        for (int nt = 0; nt < 4; nt++)
            #pragma unroll
            for (int i = 0; i < 4; i++) acc[mt][nt][i] = 0.f;

    ldtile(0);
    for (int kt = 0; kt < ktiles; kt++) {
        sttile();
        __syncthreads();
        if (kt + 1 < ktiles) ldtile(kt + 1);

        #pragma unroll
        for (int kk = 0; kk < BK / 8; kk++) {
            const int k = kk * 8;
            uint32_t a[2][4], bf[4][2];
            #pragma unroll
            for (int mt = 0; mt < 2; mt++) {
                const int r = wm * 32 + mt * 16 + g;
                a[mt][0] = __float_as_uint(As[r][k + tq]);
                a[mt][1] = __float_as_uint(As[r + 8][k + tq]);
                a[mt][2] = __float_as_uint(As[r][k + tq + 4]);
                a[mt][3] = __float_as_uint(As[r + 8][k + tq + 4]);
            }
            #pragma unroll
            for (int nt = 0; nt < 4; nt++) {
                const int n = wn * 32 + nt * 8 + g;
                bf[nt][0] = __float_as_uint(Bs[n][k + tq]);
                bf[nt][1] = __float_as_uint(Bs[n][k + tq + 4]);
            }
            #pragma unroll
            for (int mt = 0; mt < 2; mt++)
                #pragma unroll
                for (int nt = 0; nt < 4; nt++) {
                    asm volatile(
                        "mma.sync.aligned.m16n8k8.row.col.f32.tf32.tf32.f32 "
                        "{%0,%1,%2,%3}, {%4,%5,%6,%7}, {%8,%9}, {%0,%1,%2,%3};"
                        : "+f"(acc[mt][nt][0]), "+f"(acc[mt][nt][1]),
                          "+f"(acc[mt][nt][2]), "+f"(acc[mt][nt][3])
                        : "r"(a[mt][0]), "r"(a[mt][1]), "r"(a[mt][2]), "r"(a[mt][3]),
                          "r"(bf[nt][0]), "r"(bf[nt][1]));
                }
        }
        __syncthreads();
    }

    // epilogue + store
    #pragma unroll
    for (int mt = 0; mt < 2; mt++) {
        const int r = row0 + wm * 32 + mt * 16 + g;
        #pragma unroll
        for (int nt = 0; nt < 4; nt++) {
            const int c = col0 + wn * 32 + nt * 8 + 2 * tq;
            if (c < N) {
                float b0 = 0.f, b1 = 0.f;
                if (EPI != 0) { b0 = bias[c]; b1 = bias[c + 1]; }
                float2 v0, v1;
                v0.x = epi_apply<EPI>(acc[mt][nt][0], b0);
                v0.y = epi_apply<EPI>(acc[mt][nt][1], b1);
                v1.x = epi_apply<EPI>(acc[mt][nt][2], b0);
                v1.y = epi_apply<EPI>(acc[mt][nt][3], b1);
                *(float2*)&C[(size_t)r * ldc + c] = v0;
                *(float2*)&C[(size_t)(r + 8) * ldc + c] = v1;
            }
        }
    }
}

// ---------------- input transpose: (B,C,L) -> (B*L, C) ----------------
__global__ __launch_bounds__(256)
void transpose_in_kernel(const float* __restrict__ in, float* __restrict__ out)
{
    __shared__ float t[32][33];
    const int b = blockIdx.z;
    const int c0 = blockIdx.y * 32, l0 = blockIdx.x * 32;
    for (int cc = threadIdx.y; cc < 32; cc += 8)
        t[cc][threadIdx.x] = in[((size_t)b * C_IN + c0 + cc) * LEN + l0 + threadIdx.x];
    __syncthreads();
    for (int ll = threadIdx.y; ll < 32; ll += 8)
        out[((size_t)b * LEN + l0 + ll) * C_IN + c0 + threadIdx.x] = t[threadIdx.x][ll];
}

// ---------------- depthwise causal conv (D_CONV=4) + bias + silu ----------------
__global__ __launch_bounds__(256)
void conv_silu_kernel(const float* __restrict__ xz, const float* __restrict__ cw,
                      const float* __restrict__ cb, float* __restrict__ xc)
{
    const int i = blockIdx.x * 256 + threadIdx.x;   // over NROWS*512
    const int d = i & 511;
    const int r = i >> 9;
    const int l = r & (LEN - 1);
    const float* p = xz + (size_t)r * 1024 + d;
    const float4 w4 = *(const float4*)(cw + d * 4);
    float acc = cb[d];
    if (l >= 3) acc += p[-3 * 1024] * w4.x;
    if (l >= 2) acc += p[-2 * 1024] * w4.y;
    if (l >= 1) acc += p[-1 * 1024] * w4.z;
    acc += p[0] * w4.w;
    xc[(size_t)r * 512 + d] = silu_f(acc);
}

// ---------------- selective scan (fused + x*D skip + silu(z) gate) ----------------
// block: 512 threads = 32 d x 16 s; grid: (16 d-chunks, 8 batch)
__global__ __launch_bounds__(512)
void scan_kernel(const float* __restrict__ delta, const float* __restrict__ xz,
                 const float* __restrict__ xc, const float* __restrict__ xdb,
                 const float* __restrict__ A_log, const float* __restrict__ Dp,
                 float* __restrict__ y)
{
    __shared__ float sd[2][32][32], su[2][32][32], sx[2][32][32], sz[2][32][32];
    __shared__ float sB[2][32][16], sC[2][32][16];
    __shared__ float ys[32][32];
    __shared__ float sDv[32];

    const int b  = blockIdx.y;
    const int d0 = blockIdx.x * 32;
    const int tid = threadIdx.x;
    const int dl = tid >> 4, s = tid & 15;
    const int d = d0 + dl;

    const float a   = -__expf(A_log[d * 16 + s]);
    const float aL2 = a * 1.4426950408889634f;
    if (tid < 32) sDv[tid] = Dp[d0 + tid];

    const size_t rowbase = (size_t)b * LEN;

    float4 pd, px, pz, pbc;
    auto prefetch = [&](int c) {
        const int l0 = c * 32;
        if (tid < 256) {
            const int l = tid >> 3, q = tid & 7;
            const size_t r = rowbase + l0 + l;
            pd = *(const float4*)(delta + r * 512 + d0 + q * 4);
            px = *(const float4*)(xc + r * 512 + d0 + q * 4);
            const int j = tid & 127;
            const int l2 = j >> 2, q2 = j & 3;
            const size_t r2 = rowbase + l0 + l2;
            const int off = (tid < 128) ? 16 : 32;
            pbc = *(const float4*)(xdb + r2 * 48 + off + q2 * 4);
        } else {
            const int j = tid - 256;
            const int l = j >> 3, q = j & 7;
            const size_t r = rowbase + l0 + l;
            pz = *(const float4*)(xz + r * 1024 + 512 + d0 + q * 4);
        }
    };
    auto sto = [&](int buf) {
        if (tid < 256) {
            const int l = tid >> 3, q = tid & 7;
            *(float4*)&sd[buf][l][q * 4] = pd;
            *(float4*)&sx[buf][l][q * 4] = px;
            float4 u;
            u.x = pd.x * px.x; u.y = pd.y * px.y;
            u.z = pd.z * px.z; u.w = pd.w * px.w;
            *(float4*)&su[buf][l][q * 4] = u;
            const int j = tid & 127;
            const int l2 = j >> 2, q2 = j & 3;
            if (tid < 128) *(float4*)&sB[buf][l2][q2 * 4] = pbc;
            else           *(float4*)&sC[buf][l2][q2 * 4] = pbc;
        } else {
            const int j = tid - 256;
            const int l = j >> 3, q = j & 7;
            *(float4*)&sz[buf][l][q * 4] = pz;
        }
    };

    float h = 0.f;
    prefetch(0);
    sto(0);
    __syncthreads();

    const int NCH = LEN / 32;
    for (int c = 0; c < NCH; c++) {
        const int buf = c & 1;
        if (c + 1 < NCH) prefetch(c + 1);

        #pragma unroll 4
        for (int l = 0; l < 32; l++) {
            const float dt = sd[buf][l][dl];
            const float ut = su[buf][l][dl];
            const float Bv = sB[buf][l][s];
            const float Cv = sC[buf][l][s];
            float e;
            asm("ex2.approx.f32 %0, %1;" : "=f"(e) : "f"(aL2 * dt));
            h = fmaf(e, h, ut * Bv);
            float p = h * Cv;
            p += __shfl_xor_sync(0xffffffffu, p, 8);
            p += __shfl_xor_sync(0xffffffffu, p, 4);
            p += __shfl_xor_sync(0xffffffffu, p, 2);
            p += __shfl_xor_sync(0xffffffffu, p, 1);
            if (s == 0) ys[l][dl] = p;
        }
        __syncthreads();

        {   // fused epilogue: (y + xc*D) * silu(z), coalesced writes
            const int l0 = c * 32;
            #pragma unroll
            for (int i = tid; i < 1024; i += 512) {
                const int l = i >> 5, dd = i & 31;
                const float yv = ys[l][dd];
                const float xv = sx[buf][l][dd];
                const float zv = sz[buf][l][dd];
                const float outv = (yv + xv * sDv[dd]) * silu_f(zv);
                y[(rowbase + l0 + l) * 512 + d0 + dd] = outv;
            }
        }
        if (c + 1 < NCH) sto((c + 1) & 1);
        __syncthreads();
    }
}

// ---------------- final scatter: (B*L, 512) -> (2, B, 256, L) ----------------
__global__ __launch_bounds__(256)
void scatter_out_kernel(const float* __restrict__ fin, float* __restrict__ out)
{
    __shared__ float t[32][33];
    const int b = blockIdx.z;
    const int n0 = blockIdx.y * 32, l0 = blockIdx.x * 32;
    for (int ll = threadIdx.y; ll < 32; ll += 8)
        t[ll][threadIdx.x] = fin[((size_t)b * LEN + l0 + ll) * 512 + n0 + threadIdx.x];
    __syncthreads();
    for (int nn = threadIdx.y; nn < 32; nn += 8) {
        const int n = n0 + nn;
        const int spk = n >> 8, ch = n & 255;
        const size_t idx = ((size_t)(spk * BATCH + b) * C_IN + ch) * LEN + l0;
        out[idx + threadIdx.x] = t[threadIdx.x][nn];
    }
}

// ---------------- host ----------------
extern "C" void kernel_launch(void* const* d_in, const int* in_sizes, int n_in,
                              void* d_out, int out_size)
{
    (void)in_sizes; (void)n_in; (void)out_size;
    const float* input      = (const float*)d_in[0];
    const float* in_proj_w  = (const float*)d_in[1];
    const float* conv_w     = (const float*)d_in[2];
    const float* conv_b     = (const float*)d_in[3];
    const float* x_proj_w   = (const float*)d_in[4];
    const float* dt_proj_w  = (const float*)d_in[5];
    const float* dt_proj_b  = (const float*)d_in[6];
    const float* A_log      = (const float*)d_in[7];
    const float* Dw         = (const float*)d_in[8];
    const float* out_proj_w = (const float*)d_in[9];
    const float* out_lin_w  = (const float*)d_in[10];
    const float* out_lin_b  = (const float*)d_in[11];
    float* out = (float*)d_out;

    float *px, *pxz, *pxc, *pxdb, *pdelta, *py;
    cudaGetSymbolAddress((void**)&px,     g_x);
    cudaGetSymbolAddress((void**)&pxz,    g_xz);
    cudaGetSymbolAddress((void**)&pxc,    g_xc);
    cudaGetSymbolAddress((void**)&pxdb,   g_xdb);
    cudaGetSymbolAddress((void**)&pdelta, g_delta);
    cudaGetSymbolAddress((void**)&py,     g_y);

    // input (B,C,L) -> g_x (B*L, C)
    transpose_in_kernel<<<dim3(LEN / 32, C_IN / 32, BATCH), dim3(32, 8)>>>(input, px);

    for (int layer = 0; layer < 2; layer++) {
        const float* w_in   = in_proj_w  + (size_t)layer * 1024 * 256;
        const float* w_cv   = conv_w     + (size_t)layer * 512 * 4;
        const float* b_cv   = conv_b     + (size_t)layer * 512;
        const float* w_xp   = x_proj_w   + (size_t)layer * 48 * 512;
        const float* w_dt   = dt_proj_w  + (size_t)layer * 512 * 16;
        const float* b_dt   = dt_proj_b  + (size_t)layer * 512;
        const float* alog   = A_log      + (size_t)layer * 512 * 16;
        const float* dvec   = Dw         + (size_t)layer * 512;
        const float* w_out  = out_proj_w + (size_t)layer * 256 * 512;

        // in_proj: xz = x @ W^T   (N=1024, K=256)
        gemm_tf32_kernel<32, 0><<<dim3(16, NROWS / 128), 256>>>(
            px, C_IN, w_in, nullptr, pxz, 1024, 1024, 256);

        // depthwise conv + silu
        conv_silu_kernel<<<(NROWS * 512) / 256, 256>>>(pxz, w_cv, b_cv, pxc);

        // x_db = xc @ x_proj^T   (N=48, K=512)
        gemm_tf32_kernel<32, 0><<<dim3(1, NROWS / 128), 256>>>(
            pxc, 512, w_xp, nullptr, pxdb, 48, 48, 512);

        // delta = softplus(dt @ dt_proj^T + b)   (N=512, K=16)
        gemm_tf32_kernel<16, 1><<<dim3(8, NROWS / 128), 256>>>(
            pxdb, 48, w_dt, b_dt, pdelta, 512, 512, 16);

        // selective scan + D skip + silu(z) gate
        scan_kernel<<<dim3(16, BATCH), 512>>>(pdelta, pxz, pxc, pxdb, alog, dvec, py);

        // out_proj: x_next = y @ W^T   (N=256, K=512) -> overwrite g_x
        gemm_tf32_kernel<32, 0><<<dim3(4, NROWS / 128), 256>>>(
            py, 512, w_out, nullptr, px, 256, 256, 512);
    }

    // final linear + bias + relu   (N=512, K=256) -> g_y
    gemm_tf32_kernel<32, 2><<<dim3(8, NROWS / 128), 256>>>(
        px, C_IN, out_lin_w, out_lin_b, py, 512, 512, 256);

    // scatter to (NUM_SPKS, B, C, L)
    scatter_out_kernel<<<dim3(LEN / 32, 16, BATCH), dim3(32, 8)>>>(py, out);
}